// round 5
// baseline (speedup 1.0000x reference)
#include <cuda_runtime.h>

// BatchBlur: per-sample 15x15 depthwise blur with reflect pad.
// x: (32,3,512,512) f32, kernel: (32,15,15) f32, out: (32,3,512,512) f32.
// Scalar-FFMA version; ceiling is 1 FFMA/cyc/SMSP (dual fma+alu dispatch).
// R4: lift 64-reg cap (launch_bounds minBlocks=4) to eliminate local spills.

#define BB 32
#define CC 3
#define HH 512
#define WW 512
#define LL 15
#define PP 7

#define TW 128                  // output cols per CTA
#define TH 16                   // output rows per CTA
#define IN_ROWS (TH + LL - 1)   // 30
#define CH_ROW 41               // 16B chunks per smem row (odd -> 2-row bank shift)
#define ROW_F (CH_ROW * 4)      // 164 floats per smem row
#define LOAD_F 148              // floats actually loaded per row (need 142)

__device__ __forceinline__ int reflect_idx(int i, int n) {
    i = i < 0 ? -i : i;
    return i >= n ? 2 * n - 2 - i : i;
}

__global__ __launch_bounds__(128, 4) void batchblur_kernel(
    const float* __restrict__ x, const float* __restrict__ ker,
    float* __restrict__ out) {
    __shared__ __align__(16) float s_in[IN_ROWS * ROW_F];
    __shared__ __align__(16) float s_k[LL * 16];   // 15 taps + 1 pad per row

    const int tid = threadIdx.x;
    const int tx = tid & 15;     // 16 threads across x, 8 px each
    const int tyi = tid >> 4;    // 8 threads across y, 2 rows each

    const int x0 = blockIdx.x * TW;
    const int y0 = blockIdx.y * TH;
    const int img = blockIdx.z;  // b*3 + c
    const int b = img / CC;

    const float* xin = x + (size_t)img * (HH * WW);

    // kernel taps -> smem, rows padded to 16 floats for LDS.128
    for (int i = tid; i < LL * LL; i += 128) {
        int r = i / LL, c = i - r * LL;
        s_k[r * 16 + c] = ker[b * (LL * LL) + i];
    }

    // input tile: reflect pad + 16B-chunk XOR swizzle
    for (int idx = tid; idx < IN_ROWS * LOAD_F; idx += 128) {
        int r = idx / LOAD_F;
        int f = idx - r * LOAD_F;
        int gy = reflect_idx(y0 + r - PP, HH);
        int gx = reflect_idx(x0 + f - PP, WW);
        float v = xin[gy * WW + gx];
        int p = f >> 2;
        int q = p ^ ((p >> 3) & 7);
        s_in[r * ROW_F + (q << 2) + (f & 3)] = v;
    }
    __syncthreads();

    // swizzled float offsets of this thread's 6 window chunks
    int woff[6];
#pragma unroll
    for (int j = 0; j < 6; j++) {
        int c = 2 * tx + j;
        woff[j] = (c ^ ((c >> 3) & 7)) << 2;
    }

    float accA[8], accB[8];
#pragma unroll
    for (int i = 0; i < 8; i++) { accA[i] = 0.f; accB[i] = 0.f; }

    float w[24], tE[15], tO[15];

    // moving pointers: all offsets inside unrolled bodies are immediates
    const float* rp = s_in + (size_t)(2 * tyi) * ROW_F;
    const float4* kp = reinterpret_cast<const float4*>(s_k);

#define LOADW(base)                                                       \
    {                                                                     \
        _Pragma("unroll") for (int j = 0; j < 6; j++) {                   \
            float4 v_ = *reinterpret_cast<const float4*>((base) + woff[j]); \
            w[4 * j + 0] = v_.x; w[4 * j + 1] = v_.y;                     \
            w[4 * j + 2] = v_.z; w[4 * j + 3] = v_.w;                     \
        }                                                                 \
    }

#define LOADT(t, kbase)                                                   \
    {                                                                     \
        _Pragma("unroll") for (int j = 0; j < 3; j++) {                   \
            float4 v_ = (kbase)[j];                                       \
            (t)[4 * j + 0] = v_.x; (t)[4 * j + 1] = v_.y;                 \
            (t)[4 * j + 2] = v_.z; (t)[4 * j + 3] = v_.w;                 \
        }                                                                 \
        float4 v_ = (kbase)[3];                                           \
        (t)[12] = v_.x; (t)[13] = v_.y; (t)[14] = v_.z;                   \
    }

#define FMA_ONE(acc, t)                                                   \
    _Pragma("unroll") for (int dx = 0; dx < 15; dx++)                     \
        _Pragma("unroll") for (int i = 0; i < 8; i++)                     \
            (acc)[i] = fmaf(w[dx + i], (t)[dx], (acc)[i]);

#define FMA_TWO(t_a, t_b)                                                 \
    _Pragma("unroll") for (int dx = 0; dx < 15; dx++)                     \
        _Pragma("unroll") for (int i = 0; i < 8; i++) {                   \
            accA[i] = fmaf(w[dx + i], (t_a)[dx], accA[i]);                \
            accB[i] = fmaf(w[dx + i], (t_b)[dx], accB[i]);                \
        }

    // r = 0: only out-row A (kernel row 0)
    LOADW(rp);
    LOADT(tE, kp);
    FMA_ONE(accA, tE);
    rp += ROW_F;
    kp += 4;

    // r = 1..14 as 7 parity pairs; accA uses ker[r], accB uses ker[r-1]
#pragma unroll 1
    for (int it = 0; it < 7; it++) {
        LOADW(rp);
        LOADT(tO, kp);
        FMA_TWO(tO, tE);
        LOADW(rp + ROW_F);
        LOADT(tE, kp + 4);
        FMA_TWO(tE, tO);
        rp += 2 * ROW_F;
        kp += 8;
    }

    // r = 15: only out-row B (kernel row 14 == tE loaded at r=14)
    LOADW(rp);
    FMA_ONE(accB, tE);

    // direct coalesced stores: 16 lanes x 32B = contiguous 512B per row
    float* o = out + (size_t)img * (HH * WW) + (size_t)(y0 + 2 * tyi) * WW +
               x0 + 8 * tx;
    *reinterpret_cast<float4*>(o) = make_float4(accA[0], accA[1], accA[2], accA[3]);
    *reinterpret_cast<float4*>(o + 4) = make_float4(accA[4], accA[5], accA[6], accA[7]);
    *reinterpret_cast<float4*>(o + WW) = make_float4(accB[0], accB[1], accB[2], accB[3]);
    *reinterpret_cast<float4*>(o + WW + 4) = make_float4(accB[4], accB[5], accB[6], accB[7]);
}

extern "C" void kernel_launch(void* const* d_in, const int* in_sizes, int n_in,
                              void* d_out, int out_size) {
    const float* x = (const float*)d_in[0];
    const float* k = (const float*)d_in[1];
    float* out = (float*)d_out;
    dim3 grid(WW / TW, HH / TH, BB * CC);
    batchblur_kernel<<<grid, 128>>>(x, k, out);
}

// round 6
// speedup vs baseline: 1.0002x; 1.0002x over previous
#include <cuda_runtime.h>

// BatchBlur: per-sample 15x15 depthwise blur with reflect pad.
// x: (32,3,512,512) f32, kernel: (32,15,15) f32, out: (32,3,512,512) f32.
// Scalar-FFMA version; ceiling is 1 FFMA/cyc/SMSP (dual fma+alu dispatch).
// R4: lift 64-reg cap (launch_bounds minBlocks=4) to eliminate local spills.

#define BB 32
#define CC 3
#define HH 512
#define WW 512
#define LL 15
#define PP 7

#define TW 128                  // output cols per CTA
#define TH 16                   // output rows per CTA
#define IN_ROWS (TH + LL - 1)   // 30
#define CH_ROW 41               // 16B chunks per smem row (odd -> 2-row bank shift)
#define ROW_F (CH_ROW * 4)      // 164 floats per smem row
#define LOAD_F 148              // floats actually loaded per row (need 142)

__device__ __forceinline__ int reflect_idx(int i, int n) {
    i = i < 0 ? -i : i;
    return i >= n ? 2 * n - 2 - i : i;
}

__global__ __launch_bounds__(128, 4) void batchblur_kernel(
    const float* __restrict__ x, const float* __restrict__ ker,
    float* __restrict__ out) {
    __shared__ __align__(16) float s_in[IN_ROWS * ROW_F];
    __shared__ __align__(16) float s_k[LL * 16];   // 15 taps + 1 pad per row

    const int tid = threadIdx.x;
    const int tx = tid & 15;     // 16 threads across x, 8 px each
    const int tyi = tid >> 4;    // 8 threads across y, 2 rows each

    const int x0 = blockIdx.x * TW;
    const int y0 = blockIdx.y * TH;
    const int img = blockIdx.z;  // b*3 + c
    const int b = img / CC;

    const float* xin = x + (size_t)img * (HH * WW);

    // kernel taps -> smem, rows padded to 16 floats for LDS.128
    for (int i = tid; i < LL * LL; i += 128) {
        int r = i / LL, c = i - r * LL;
        s_k[r * 16 + c] = ker[b * (LL * LL) + i];
    }

    // input tile: reflect pad + 16B-chunk XOR swizzle
    for (int idx = tid; idx < IN_ROWS * LOAD_F; idx += 128) {
        int r = idx / LOAD_F;
        int f = idx - r * LOAD_F;
        int gy = reflect_idx(y0 + r - PP, HH);
        int gx = reflect_idx(x0 + f - PP, WW);
        float v = xin[gy * WW + gx];
        int p = f >> 2;
        int q = p ^ ((p >> 3) & 7);
        s_in[r * ROW_F + (q << 2) + (f & 3)] = v;
    }
    __syncthreads();

    // swizzled float offsets of this thread's 6 window chunks
    int woff[6];
#pragma unroll
    for (int j = 0; j < 6; j++) {
        int c = 2 * tx + j;
        woff[j] = (c ^ ((c >> 3) & 7)) << 2;
    }

    float accA[8], accB[8];
#pragma unroll
    for (int i = 0; i < 8; i++) { accA[i] = 0.f; accB[i] = 0.f; }

    float w[24], tE[15], tO[15];

    // moving pointers: all offsets inside unrolled bodies are immediates
    const float* rp = s_in + (size_t)(2 * tyi) * ROW_F;
    const float4* kp = reinterpret_cast<const float4*>(s_k);

#define LOADW(base)                                                       \
    {                                                                     \
        _Pragma("unroll") for (int j = 0; j < 6; j++) {                   \
            float4 v_ = *reinterpret_cast<const float4*>((base) + woff[j]); \
            w[4 * j + 0] = v_.x; w[4 * j + 1] = v_.y;                     \
            w[4 * j + 2] = v_.z; w[4 * j + 3] = v_.w;                     \
        }                                                                 \
    }

#define LOADT(t, kbase)                                                   \
    {                                                                     \
        _Pragma("unroll") for (int j = 0; j < 3; j++) {                   \
            float4 v_ = (kbase)[j];                                       \
            (t)[4 * j + 0] = v_.x; (t)[4 * j + 1] = v_.y;                 \
            (t)[4 * j + 2] = v_.z; (t)[4 * j + 3] = v_.w;                 \
        }                                                                 \
        float4 v_ = (kbase)[3];                                           \
        (t)[12] = v_.x; (t)[13] = v_.y; (t)[14] = v_.z;                   \
    }

#define FMA_ONE(acc, t)                                                   \
    _Pragma("unroll") for (int dx = 0; dx < 15; dx++)                     \
        _Pragma("unroll") for (int i = 0; i < 8; i++)                     \
            (acc)[i] = fmaf(w[dx + i], (t)[dx], (acc)[i]);

#define FMA_TWO(t_a, t_b)                                                 \
    _Pragma("unroll") for (int dx = 0; dx < 15; dx++)                     \
        _Pragma("unroll") for (int i = 0; i < 8; i++) {                   \
            accA[i] = fmaf(w[dx + i], (t_a)[dx], accA[i]);                \
            accB[i] = fmaf(w[dx + i], (t_b)[dx], accB[i]);                \
        }

    // r = 0: only out-row A (kernel row 0)
    LOADW(rp);
    LOADT(tE, kp);
    FMA_ONE(accA, tE);
    rp += ROW_F;
    kp += 4;

    // r = 1..14 as 7 parity pairs; accA uses ker[r], accB uses ker[r-1]
#pragma unroll 1
    for (int it = 0; it < 7; it++) {
        LOADW(rp);
        LOADT(tO, kp);
        FMA_TWO(tO, tE);
        LOADW(rp + ROW_F);
        LOADT(tE, kp + 4);
        FMA_TWO(tE, tO);
        rp += 2 * ROW_F;
        kp += 8;
    }

    // r = 15: only out-row B (kernel row 14 == tE loaded at r=14)
    LOADW(rp);
    FMA_ONE(accB, tE);

    // direct coalesced stores: 16 lanes x 32B = contiguous 512B per row
    float* o = out + (size_t)img * (HH * WW) + (size_t)(y0 + 2 * tyi) * WW +
               x0 + 8 * tx;
    *reinterpret_cast<float4*>(o) = make_float4(accA[0], accA[1], accA[2], accA[3]);
    *reinterpret_cast<float4*>(o + 4) = make_float4(accA[4], accA[5], accA[6], accA[7]);
    *reinterpret_cast<float4*>(o + WW) = make_float4(accB[0], accB[1], accB[2], accB[3]);
    *reinterpret_cast<float4*>(o + WW + 4) = make_float4(accB[4], accB[5], accB[6], accB[7]);
}

extern "C" void kernel_launch(void* const* d_in, const int* in_sizes, int n_in,
                              void* d_out, int out_size) {
    const float* x = (const float*)d_in[0];
    const float* k = (const float*)d_in[1];
    float* out = (float*)d_out;
    dim3 grid(WW / TW, HH / TH, BB * CC);
    batchblur_kernel<<<grid, 128>>>(x, k, out);
}

// round 7
// speedup vs baseline: 1.0807x; 1.0804x over previous
#include <cuda_runtime.h>

// BatchBlur: per-sample 15x15 depthwise blur with reflect pad.
// x: (32,3,512,512) f32, kernel: (32,15,15) f32, out: (32,3,512,512) f32.
// Scalar-FFMA, issue-slot bound (1 FFMA/cyc/SMSP across fma+alu pipes).
// R5: 16px x 2rows per thread -> 480 FFMA per 12 LDS.128; literal indexing.

#define BB 32
#define CC 3
#define HH 512
#define WW 512
#define LL 15
#define PP 7

#define TW 128                  // output cols per CTA (8 threads x 16 px)
#define TH 32                   // output rows per CTA (16 threads x 2 rows)
#define IN_ROWS (TH + LL - 1)   // 46
#define CH_ROW 41               // 16B chunks per smem row (odd; swizzle q<=39)
#define ROW_F (CH_ROW * 4)      // 164 floats per smem row
#define LOAD_F 144              // floats loaded per row (need 142)

__device__ __forceinline__ int reflect_idx(int i, int n) {
    i = i < 0 ? -i : i;
    return i >= n ? 2 * n - 2 - i : i;
}

__global__ __launch_bounds__(128, 4) void batchblur_kernel(
    const float* __restrict__ x, const float* __restrict__ ker,
    float* __restrict__ out) {
    __shared__ __align__(16) float s_in[IN_ROWS * ROW_F];
    __shared__ __align__(16) float s_k[LL * 16];   // 15 taps + 1 pad per row

    const int tid = threadIdx.x;
    const int tx = tid & 7;      // 8 threads across x, 16 px each
    const int tyi = tid >> 3;    // 16 threads across y, 2 rows each

    const int x0 = blockIdx.x * TW;
    const int y0 = blockIdx.y * TH;
    const int img = blockIdx.z;  // b*3 + c
    const int b = img / CC;

    const float* xin = x + (size_t)img * (HH * WW);

    // kernel taps -> smem, rows padded to 16 floats for LDS.128
    for (int i = tid; i < LL * LL; i += 128) {
        int r = i / LL, c = i - r * LL;
        s_k[r * 16 + c] = ker[b * (LL * LL) + i];
    }

    // input tile: reflect pad + 16B-chunk XOR swizzle
    for (int idx = tid; idx < IN_ROWS * LOAD_F; idx += 128) {
        int r = idx / LOAD_F;
        int f = idx - r * LOAD_F;
        int gy = reflect_idx(y0 + r - PP, HH);
        int gx = reflect_idx(x0 + f - PP, WW);
        float v = xin[gy * WW + gx];
        int p = f >> 2;
        int q = p ^ ((p >> 3) & 7);
        s_in[r * ROW_F + (q << 2) + (f & 3)] = v;
    }
    __syncthreads();

    // swizzled float offsets of this thread's 8 window chunks
    int woff[8];
#pragma unroll
    for (int j = 0; j < 8; j++) {
        int c = 4 * tx + j;
        woff[j] = (c ^ ((c >> 3) & 7)) << 2;
    }

    float accA[16], accB[16];
#pragma unroll
    for (int i = 0; i < 16; i++) { accA[i] = 0.f; accB[i] = 0.f; }

    float w[32], tE[15], tO[15];

    const float* rowbase = s_in + (size_t)(2 * tyi) * ROW_F;

#define LOADW(r)                                                          \
    {                                                                     \
        const float* rp_ = rowbase + (r) * ROW_F;                         \
        _Pragma("unroll") for (int j = 0; j < 8; j++) {                   \
            float4 v_ = *reinterpret_cast<const float4*>(rp_ + woff[j]);  \
            w[4 * j + 0] = v_.x; w[4 * j + 1] = v_.y;                     \
            w[4 * j + 2] = v_.z; w[4 * j + 3] = v_.w;                     \
        }                                                                 \
    }

#define LOADT(t, r)                                                       \
    {                                                                     \
        const float4* k4_ = reinterpret_cast<const float4*>(s_k + (r) * 16); \
        _Pragma("unroll") for (int j = 0; j < 3; j++) {                   \
            float4 v_ = k4_[j];                                           \
            (t)[4 * j + 0] = v_.x; (t)[4 * j + 1] = v_.y;                 \
            (t)[4 * j + 2] = v_.z; (t)[4 * j + 3] = v_.w;                 \
        }                                                                 \
        float4 v_ = k4_[3];                                               \
        (t)[12] = v_.x; (t)[13] = v_.y; (t)[14] = v_.z;                   \
    }

#define FMA_ONE(acc, t)                                                   \
    _Pragma("unroll") for (int dx = 0; dx < 15; dx++)                     \
        _Pragma("unroll") for (int i = 0; i < 16; i++)                    \
            (acc)[i] = fmaf(w[dx + i], (t)[dx], (acc)[i]);

#define FMA_TWO(t_a, t_b)                                                 \
    _Pragma("unroll") for (int dx = 0; dx < 15; dx++)                     \
        _Pragma("unroll") for (int i = 0; i < 16; i++) {                  \
            accA[i] = fmaf(w[dx + i], (t_a)[dx], accA[i]);                \
            accB[i] = fmaf(w[dx + i], (t_b)[dx], accB[i]);                \
        }

    // r = 0: only out-row A (kernel row 0)
    LOADW(0);
    LOADT(tE, 0);
    FMA_ONE(accA, tE);

    // r = 1..14 as 7 parity pairs; accA uses ker[r], accB uses ker[r-1]
#pragma unroll 1
    for (int rp = 0; rp < 7; rp++) {
        int r = 2 * rp + 1;
        LOADW(r);
        LOADT(tO, r);
        FMA_TWO(tO, tE);
        LOADW(r + 1);
        LOADT(tE, r + 1);
        FMA_TWO(tE, tO);
    }

    // r = 15: only out-row B (kernel row 14 == tE loaded at r=14)
    LOADW(15);
    FMA_ONE(accB, tE);

    // direct stores: each thread writes 64B contiguous per row
    float* o = out + (size_t)img * (HH * WW) + (size_t)(y0 + 2 * tyi) * WW +
               x0 + 16 * tx;
#pragma unroll
    for (int j = 0; j < 4; j++) {
        *reinterpret_cast<float4*>(o + 4 * j) =
            make_float4(accA[4 * j], accA[4 * j + 1], accA[4 * j + 2], accA[4 * j + 3]);
        *reinterpret_cast<float4*>(o + WW + 4 * j) =
            make_float4(accB[4 * j], accB[4 * j + 1], accB[4 * j + 2], accB[4 * j + 3]);
    }
}

extern "C" void kernel_launch(void* const* d_in, const int* in_sizes, int n_in,
                              void* d_out, int out_size) {
    const float* x = (const float*)d_in[0];
    const float* k = (const float*)d_in[1];
    float* out = (float*)d_out;
    dim3 grid(WW / TW, HH / TH, BB * CC);
    batchblur_kernel<<<grid, 128>>>(x, k, out);
}